// round 12
// baseline (speedup 1.0000x reference)
#include <cuda_runtime.h>
#include <cuda_bf16.h>
#include <cstdint>
#include <math.h>

#define BSZ 2
#define SEQ 4096
#define DIM 512
#define NH  8
#define HDIM 64
#define NELEM (BSZ*NH*SEQ*HDIM)
#define MTOT (BSZ*SEQ)

// Scratch (no cudaMalloc). All operands stored as hi/lo split bf16.
__device__ __nv_bfloat16 g_Qh[NELEM], g_Ql[NELEM];
__device__ __nv_bfloat16 g_Kh[NELEM], g_Kl[NELEM];
__device__ __nv_bfloat16 g_Vh[NELEM], g_Vl[NELEM];   // transposed [b,h,hd,s]
__device__ __nv_bfloat16 g_Xh[MTOT*DIM], g_Xl[MTOT*DIM];
__device__ __nv_bfloat16 g_Wqh[3*DIM*DIM], g_Wql[3*DIM*DIM];
__device__ __nv_bfloat16 g_Woh[DIM*DIM], g_Wol[DIM*DIM];
__device__ __nv_bfloat16 g_Yh[MTOT*DIM], g_Yl[MTOT*DIM];

// ---------------------------------------------------------------------------
__device__ __forceinline__ void mma16816(float* c, const uint32_t* a, const uint32_t* b) {
    asm volatile(
        "mma.sync.aligned.m16n8k16.row.col.f32.bf16.bf16.f32 "
        "{%0,%1,%2,%3}, {%4,%5,%6,%7}, {%8,%9}, {%0,%1,%2,%3};"
        : "+f"(c[0]), "+f"(c[1]), "+f"(c[2]), "+f"(c[3])
        : "r"(a[0]), "r"(a[1]), "r"(a[2]), "r"(a[3]), "r"(b[0]), "r"(b[1]));
}
__device__ __forceinline__ void split2(float v, __nv_bfloat16& h, __nv_bfloat16& l) {
    h = __float2bfloat16(v);
    l = __float2bfloat16(v - __bfloat162float(h));
}
__device__ __forceinline__ void packsplit(float x, float y, uint32_t& hi, uint32_t& lo) {
    __nv_bfloat16 hx, lx, hy, ly;
    split2(x, hx, lx); split2(y, hy, ly);
    __nv_bfloat162 h2 = __halves2bfloat162(hx, hy);
    __nv_bfloat162 l2 = __halves2bfloat162(lx, ly);
    hi = *(uint32_t*)&h2; lo = *(uint32_t*)&l2;
}

// ---------------------------------------------------------------------------
// Pre-split: fp32 -> (hi, lo) bf16, vectorized x4
// ---------------------------------------------------------------------------
__global__ void split_f32(const float* __restrict__ in,
                          __nv_bfloat16* __restrict__ oh,
                          __nv_bfloat16* __restrict__ ol, int n4)
{
    int i = blockIdx.x * blockDim.x + threadIdx.x;
    if (i < n4) {
        float4 f = ((const float4*)in)[i];
        uint32_t h0, l0, h1, l1;
        packsplit(f.x, f.y, h0, l0);
        packsplit(f.z, f.w, h1, l1);
        ((uint2*)oh)[i] = make_uint2(h0, h1);
        ((uint2*)ol)[i] = make_uint2(l0, l1);
    }
}

// ---------------------------------------------------------------------------
// GEMM on pre-split operands: C = A @ W^T + bias (3-pass hi/lo MMA).
// Block 128x128, 256 threads (8 warps: 4m x 2n), K-chunk 32.
// MODE 0: fp32 store. MODE 1: QKV split scatter.
// ---------------------------------------------------------------------------
#define GSTR 40

template<int MODE>
__launch_bounds__(256)
__global__ void gemm_mma(const __nv_bfloat16* __restrict__ Ah, const __nv_bfloat16* __restrict__ Al,
                         const __nv_bfloat16* __restrict__ Wh, const __nv_bfloat16* __restrict__ Wl,
                         const float* __restrict__ bias, float* __restrict__ C,
                         int M, int N, int K)
{
    __shared__ __nv_bfloat16 sAh[128][GSTR], sAl[128][GSTR];
    __shared__ __nv_bfloat16 sBh[128][GSTR], sBl[128][GSTR];

    const int tid = threadIdx.x;
    const int lane = tid & 31, wid = tid >> 5;
    const int gid = lane >> 2, tig = lane & 3;
    const int wm = (wid >> 1) * 32, wn = (wid & 1) * 64;
    const int m0 = blockIdx.y * 128, n0 = blockIdx.x * 128;

    float acc[2][8][4];
    #pragma unroll
    for (int mt = 0; mt < 2; mt++)
        #pragma unroll
        for (int nt = 0; nt < 8; nt++)
            #pragma unroll
            for (int q = 0; q < 4; q++) acc[mt][nt][q] = 0.f;

    for (int k0 = 0; k0 < K; k0 += 32) {
        // stage: pure uint4 copies (8 bf16 each)
        #pragma unroll
        for (int i = 0; i < 2; i++) {
            int idx = tid + i * 256;        // 0..511
            int r = idx >> 2, c = (idx & 3) * 8;
            size_t ga = (size_t)(m0 + r) * K + k0 + c;
            size_t gw = (size_t)(n0 + r) * K + k0 + c;
            *(uint4*)&sAh[r][c] = *(const uint4*)&Ah[ga];
            *(uint4*)&sAl[r][c] = *(const uint4*)&Al[ga];
            *(uint4*)&sBh[r][c] = *(const uint4*)&Wh[gw];
            *(uint4*)&sBl[r][c] = *(const uint4*)&Wl[gw];
        }
        __syncthreads();

        #pragma unroll
        for (int kk = 0; kk < 32; kk += 16) {
            uint32_t ah[2][4], al[2][4];
            #pragma unroll
            for (int mt = 0; mt < 2; mt++) {
                int r = wm + mt * 16 + gid;
                ah[mt][0] = *(uint32_t*)&sAh[r    ][kk + tig*2];
                ah[mt][1] = *(uint32_t*)&sAh[r + 8][kk + tig*2];
                ah[mt][2] = *(uint32_t*)&sAh[r    ][kk + tig*2 + 8];
                ah[mt][3] = *(uint32_t*)&sAh[r + 8][kk + tig*2 + 8];
                al[mt][0] = *(uint32_t*)&sAl[r    ][kk + tig*2];
                al[mt][1] = *(uint32_t*)&sAl[r + 8][kk + tig*2];
                al[mt][2] = *(uint32_t*)&sAl[r    ][kk + tig*2 + 8];
                al[mt][3] = *(uint32_t*)&sAl[r + 8][kk + tig*2 + 8];
            }
            uint32_t bh[8][2], bl[8][2];
            #pragma unroll
            for (int nt = 0; nt < 8; nt++) {
                int rn = wn + nt * 8 + gid;
                bh[nt][0] = *(uint32_t*)&sBh[rn][kk + tig*2];
                bh[nt][1] = *(uint32_t*)&sBh[rn][kk + tig*2 + 8];
                bl[nt][0] = *(uint32_t*)&sBl[rn][kk + tig*2];
                bl[nt][1] = *(uint32_t*)&sBl[rn][kk + tig*2 + 8];
            }
            #pragma unroll
            for (int mt = 0; mt < 2; mt++)
                #pragma unroll
                for (int nt = 0; nt < 8; nt++) {
                    mma16816(acc[mt][nt], ah[mt], bh[nt]);
                    mma16816(acc[mt][nt], ah[mt], bl[nt]);
                    mma16816(acc[mt][nt], al[mt], bh[nt]);
                }
        }
        __syncthreads();
    }

    // Epilogue
    #pragma unroll
    for (int mt = 0; mt < 2; mt++) {
        #pragma unroll
        for (int ih = 0; ih < 2; ih++) {
            int m = m0 + wm + mt * 16 + gid + ih * 8;
            #pragma unroll
            for (int nt = 0; nt < 8; nt++) {
                int n = n0 + wn + nt * 8 + tig * 2;
                float v0 = acc[mt][nt][ih*2 + 0] + __ldg(&bias[n]);
                float v1 = acc[mt][nt][ih*2 + 1] + __ldg(&bias[n + 1]);
                if (MODE == 0) {
                    float2 o2 = { v0, v1 };
                    *(float2*)&C[(size_t)m * N + n] = o2;
                } else {
                    int which = n >> 9, hh = (n >> 6) & 7, dd = n & 63;
                    int bb = m >> 12, s = m & 4095;
                    if (which == 0) {
                        size_t base = (((size_t)(bb * NH + hh) * SEQ) + s) * HDIM + dd;
                        uint32_t hi, lo;
                        packsplit(v0 * 0.125f, v1 * 0.125f, hi, lo);
                        *(uint32_t*)&g_Qh[base] = hi;
                        *(uint32_t*)&g_Ql[base] = lo;
                    } else if (which == 1) {
                        size_t base = (((size_t)(bb * NH + hh) * SEQ) + s) * HDIM + dd;
                        uint32_t hi, lo;
                        packsplit(v0, v1, hi, lo);
                        *(uint32_t*)&g_Kh[base] = hi;
                        *(uint32_t*)&g_Kl[base] = lo;
                    } else {
                        size_t base = ((size_t)(bb * NH + hh) * HDIM + dd) * SEQ + s;
                        __nv_bfloat16 h0, l0, h1, l1;
                        split2(v0, h0, l0); split2(v1, h1, l1);
                        g_Vh[base] = h0;       g_Vl[base] = l0;
                        g_Vh[base + SEQ] = h1; g_Vl[base + SEQ] = l1;
                    }
                }
            }
        }
    }
}

// ---------------------------------------------------------------------------
// Flash attention: Br=128, Bc=64, 8 warps / 256 threads (warp tile 16x64).
// S 3-pass split; register softmax (4-lane shfl); P from accumulators; P@V 3-pass.
// Epilogue writes split bf16 Y.
// ---------------------------------------------------------------------------
#define FSTR 72
#define QH_OFF 0
#define QL_OFF (128*FSTR*2)
#define KH_OFF (QL_OFF + 128*FSTR*2)
#define KL_OFF (KH_OFF + 64*FSTR*2)
#define VH_OFF (KL_OFF + 64*FSTR*2)
#define VL_OFF (VH_OFF + 64*FSTR*2)
#define FL_SMEM (VL_OFF + 64*FSTR*2)   // 73728 bytes

__launch_bounds__(256)
__global__ void flash_mma()
{
    extern __shared__ char smem[];
    __nv_bfloat16* QH = (__nv_bfloat16*)(smem + QH_OFF);
    __nv_bfloat16* QL = (__nv_bfloat16*)(smem + QL_OFF);
    __nv_bfloat16* KH = (__nv_bfloat16*)(smem + KH_OFF);
    __nv_bfloat16* KL = (__nv_bfloat16*)(smem + KL_OFF);
    __nv_bfloat16* VH = (__nv_bfloat16*)(smem + VH_OFF);
    __nv_bfloat16* VL = (__nv_bfloat16*)(smem + VL_OFF);

    const int tid = threadIdx.x;
    const int lane = tid & 31, wid = tid >> 5;   // wid 0..7
    const int gid = lane >> 2, tig = lane & 3;
    const int qt = (gridDim.x - 1) - blockIdx.x;
    const int head = blockIdx.y;
    const int b = blockIdx.z;

    const size_t bh = (size_t)(b * NH + head);
    const __nv_bfloat16* Qhp = g_Qh + (bh * SEQ + qt * 128) * HDIM;
    const __nv_bfloat16* Qlp = g_Ql + (bh * SEQ + qt * 128) * HDIM;

    // Q tile 128x64 (each buffer)
    #pragma unroll
    for (int i = 0; i < 4; i++) {
        int idx = tid + i * 256;
        int r = idx >> 3, c = (idx & 7) * 8;
        *(uint4*)&QH[r * FSTR + c] = *(const uint4*)&Qhp[r * 64 + c];
        *(uint4*)&QL[r * FSTR + c] = *(const uint4*)&Qlp[r * 64 + c];
    }

    float m_i[2], l_i[2];
    float o[8][4];
    #pragma unroll
    for (int t = 0; t < 2; t++) { m_i[t] = -1e30f; l_i[t] = 0.f; }
    #pragma unroll
    for (int ot = 0; ot < 8; ot++)
        #pragma unroll
        for (int q = 0; q < 4; q++) o[ot][q] = 0.f;

    const int qtr = qt * 128;
    const int nkt = 2 * (qt + 1);

    for (int kt = 0; kt < nkt; kt++) {
        const int kv0 = kt * 64;
        const __nv_bfloat16* Khp = g_Kh + (bh * SEQ + kv0) * HDIM;
        const __nv_bfloat16* Klp = g_Kl + (bh * SEQ + kv0) * HDIM;
        const __nv_bfloat16* Vhp = g_Vh + bh * HDIM * SEQ;
        const __nv_bfloat16* Vlp = g_Vl + bh * HDIM * SEQ;

        __syncthreads();
        #pragma unroll
        for (int i = 0; i < 2; i++) {
            int idx = tid + i * 256;
            int r = idx >> 3, c = (idx & 7) * 8;
            *(uint4*)&KH[r * FSTR + c] = *(const uint4*)&Khp[r * 64 + c];
            *(uint4*)&KL[r * FSTR + c] = *(const uint4*)&Klp[r * 64 + c];
            *(uint4*)&VH[r * FSTR + c] = *(const uint4*)&Vhp[(size_t)r * SEQ + kv0 + c];
            *(uint4*)&VL[r * FSTR + c] = *(const uint4*)&Vlp[(size_t)r * SEQ + kv0 + c];
        }
        __syncthreads();

        // ---- S = Q @ K^T ----
        float s[8][4];
        #pragma unroll
        for (int nt = 0; nt < 8; nt++)
            #pragma unroll
            for (int q = 0; q < 4; q++) s[nt][q] = 0.f;

        #pragma unroll
        for (int ks = 0; ks < 4; ks++) {
            int k0 = ks * 16;
            int r = wid * 16 + gid;
            uint32_t ah[4], al[4];
            ah[0] = *(uint32_t*)&QH[(r    ) * FSTR + k0 + tig*2];
            ah[1] = *(uint32_t*)&QH[(r + 8) * FSTR + k0 + tig*2];
            ah[2] = *(uint32_t*)&QH[(r    ) * FSTR + k0 + tig*2 + 8];
            ah[3] = *(uint32_t*)&QH[(r + 8) * FSTR + k0 + tig*2 + 8];
            al[0] = *(uint32_t*)&QL[(r    ) * FSTR + k0 + tig*2];
            al[1] = *(uint32_t*)&QL[(r + 8) * FSTR + k0 + tig*2];
            al[2] = *(uint32_t*)&QL[(r    ) * FSTR + k0 + tig*2 + 8];
            al[3] = *(uint32_t*)&QL[(r + 8) * FSTR + k0 + tig*2 + 8];
            uint32_t bhf[8][2], blf[8][2];
            #pragma unroll
            for (int nt = 0; nt < 8; nt++) {
                int rn = nt * 8 + gid;
                bhf[nt][0] = *(uint32_t*)&KH[rn * FSTR + k0 + tig*2];
                bhf[nt][1] = *(uint32_t*)&KH[rn * FSTR + k0 + tig*2 + 8];
                blf[nt][0] = *(uint32_t*)&KL[rn * FSTR + k0 + tig*2];
                blf[nt][1] = *(uint32_t*)&KL[rn * FSTR + k0 + tig*2 + 8];
            }
            #pragma unroll
            for (int nt = 0; nt < 8; nt++) {
                mma16816(s[nt], ah, bhf[nt]);
                mma16816(s[nt], ah, blf[nt]);
                mma16816(s[nt], al, bhf[nt]);
            }
        }

        // ---- causal mask ----
        if (kt >= 2 * qt) {
            int row0 = qtr + wid * 16 + gid;
            #pragma unroll
            for (int nt = 0; nt < 8; nt++) {
                int colb = kv0 + nt * 8 + tig * 2;
                if (colb     > row0    ) s[nt][0] = -1e30f;
                if (colb + 1 > row0    ) s[nt][1] = -1e30f;
                if (colb     > row0 + 8) s[nt][2] = -1e30f;
                if (colb + 1 > row0 + 8) s[nt][3] = -1e30f;
            }
        }

        // ---- online softmax ----
        #pragma unroll
        for (int ih = 0; ih < 2; ih++) {
            float mx = m_i[ih];
            #pragma unroll
            for (int nt = 0; nt < 8; nt++)
                mx = fmaxf(mx, fmaxf(s[nt][ih*2], s[nt][ih*2+1]));
            mx = fmaxf(mx, __shfl_xor_sync(0xffffffffu, mx, 1));
            mx = fmaxf(mx, __shfl_xor_sync(0xffffffffu, mx, 2));
            float corr = __expf(m_i[ih] - mx);
            float sum = 0.f;
            #pragma unroll
            for (int nt = 0; nt < 8; nt++) {
                float p0 = __expf(s[nt][ih*2]   - mx);
                float p1 = __expf(s[nt][ih*2+1] - mx);
                s[nt][ih*2]   = p0;
                s[nt][ih*2+1] = p1;
                sum += p0 + p1;
            }
            sum += __shfl_xor_sync(0xffffffffu, sum, 1);
            sum += __shfl_xor_sync(0xffffffffu, sum, 2);
            l_i[ih] = l_i[ih] * corr + sum;
            m_i[ih] = mx;
            #pragma unroll
            for (int ot = 0; ot < 8; ot++) {
                o[ot][ih*2]   *= corr;
                o[ot][ih*2+1] *= corr;
            }
        }

        // ---- O += P @ V ----
        #pragma unroll
        for (int ks = 0; ks < 4; ks++) {
            uint32_t pah[4], pal[4];
            packsplit(s[2*ks  ][0], s[2*ks  ][1], pah[0], pal[0]);
            packsplit(s[2*ks  ][2], s[2*ks  ][3], pah[1], pal[1]);
            packsplit(s[2*ks+1][0], s[2*ks+1][1], pah[2], pal[2]);
            packsplit(s[2*ks+1][2], s[2*ks+1][3], pah[3], pal[3]);
            uint32_t vbh[8][2], vbl[8][2];
            #pragma unroll
            for (int ot = 0; ot < 8; ot++) {
                int rn = ot * 8 + gid;
                vbh[ot][0] = *(uint32_t*)&VH[rn * FSTR + ks*16 + tig*2];
                vbh[ot][1] = *(uint32_t*)&VH[rn * FSTR + ks*16 + tig*2 + 8];
                vbl[ot][0] = *(uint32_t*)&VL[rn * FSTR + ks*16 + tig*2];
                vbl[ot][1] = *(uint32_t*)&VL[rn * FSTR + ks*16 + tig*2 + 8];
            }
            #pragma unroll
            for (int ot = 0; ot < 8; ot++) {
                mma16816(o[ot], pah, vbh[ot]);
                mma16816(o[ot], pal, vbh[ot]);
                mma16816(o[ot], pah, vbl[ot]);
            }
        }
    }

    // ---- epilogue: normalize, write split bf16 Y ----
    size_t Ybase = ((size_t)b * SEQ + qtr) * DIM + head * HDIM;
    #pragma unroll
    for (int ih = 0; ih < 2; ih++) {
        float inv = 1.0f / l_i[ih];
        int rl = wid * 16 + gid + ih * 8;
        #pragma unroll
        for (int ot = 0; ot < 8; ot++) {
            uint32_t hi, lo;
            packsplit(o[ot][ih*2] * inv, o[ot][ih*2+1] * inv, hi, lo);
            size_t off = Ybase + (size_t)rl * DIM + ot * 8 + tig * 2;
            *(uint32_t*)&g_Yh[off] = hi;
            *(uint32_t*)&g_Yl[off] = lo;
        }
    }
}

// ---------------------------------------------------------------------------
extern "C" void kernel_launch(void* const* d_in, const int* in_sizes, int n_in,
                              void* d_out, int out_size)
{
    const float* x    = (const float*)d_in[0];   // [2,4096,512]
    const float* Wqkv = (const float*)d_in[1];   // [1536,512]
    const float* bqkv = (const float*)d_in[2];   // [1536]
    const float* Wo   = (const float*)d_in[3];   // [512,512]
    const float* bo   = (const float*)d_in[4];   // [512]
    float* out = (float*)d_out;                  // [2,4096,512]

    void *xh, *xl, *wqh, *wql, *woh, *wol, *yh, *yl;
    cudaGetSymbolAddress(&xh,  g_Xh);  cudaGetSymbolAddress(&xl,  g_Xl);
    cudaGetSymbolAddress(&wqh, g_Wqh); cudaGetSymbolAddress(&wql, g_Wql);
    cudaGetSymbolAddress(&woh, g_Woh); cudaGetSymbolAddress(&wol, g_Wol);
    cudaGetSymbolAddress(&yh,  g_Yh);  cudaGetSymbolAddress(&yl,  g_Yl);

    cudaFuncSetAttribute(flash_mma, cudaFuncAttributeMaxDynamicSharedMemorySize, FL_SMEM);

    const int M = BSZ * SEQ;   // 8192

    // pre-split inputs
    split_f32<<<(M*DIM/4 + 255)/256, 256>>>(x, (__nv_bfloat16*)xh, (__nv_bfloat16*)xl, M*DIM/4);
    split_f32<<<(3*DIM*DIM/4 + 255)/256, 256>>>(Wqkv, (__nv_bfloat16*)wqh, (__nv_bfloat16*)wql, 3*DIM*DIM/4);
    split_f32<<<(DIM*DIM/4 + 255)/256, 256>>>(Wo, (__nv_bfloat16*)woh, (__nv_bfloat16*)wol, DIM*DIM/4);

    gemm_mma<1><<<dim3(12, 64), 256>>>((const __nv_bfloat16*)xh, (const __nv_bfloat16*)xl,
                                       (const __nv_bfloat16*)wqh, (const __nv_bfloat16*)wql,
                                       bqkv, nullptr, M, 3 * DIM, DIM);
    flash_mma<<<dim3(SEQ / 128, NH, BSZ), 256, FL_SMEM>>>();
    gemm_mma<0><<<dim3(4, 64), 256>>>((const __nv_bfloat16*)yh, (const __nv_bfloat16*)yl,
                                      (const __nv_bfloat16*)woh, (const __nv_bfloat16*)wol,
                                      bo, out, M, DIM, DIM);
}

// round 13
// speedup vs baseline: 1.0671x; 1.0671x over previous
#include <cuda_runtime.h>
#include <cuda_bf16.h>
#include <cstdint>
#include <math.h>

#define BSZ 2
#define SEQ 4096
#define DIM 512
#define NH  8
#define HDIM 64
#define NELEM (BSZ*NH*SEQ*HDIM)
#define MTOT (BSZ*SEQ)

// Scratch (no cudaMalloc). All operands stored as hi/lo split bf16.
__device__ __nv_bfloat16 g_Qh[NELEM], g_Ql[NELEM];
__device__ __nv_bfloat16 g_Kh[NELEM], g_Kl[NELEM];
__device__ __nv_bfloat16 g_Vh[NELEM], g_Vl[NELEM];   // transposed [b,h,hd,s]
__device__ __nv_bfloat16 g_Xh[MTOT*DIM], g_Xl[MTOT*DIM];
__device__ __nv_bfloat16 g_Wqh[3*DIM*DIM], g_Wql[3*DIM*DIM];
__device__ __nv_bfloat16 g_Woh[DIM*DIM], g_Wol[DIM*DIM];
__device__ __nv_bfloat16 g_Yh[MTOT*DIM], g_Yl[MTOT*DIM];

// ---------------------------------------------------------------------------
__device__ __forceinline__ void mma16816(float* c, const uint32_t* a, const uint32_t* b) {
    asm volatile(
        "mma.sync.aligned.m16n8k16.row.col.f32.bf16.bf16.f32 "
        "{%0,%1,%2,%3}, {%4,%5,%6,%7}, {%8,%9}, {%0,%1,%2,%3};"
        : "+f"(c[0]), "+f"(c[1]), "+f"(c[2]), "+f"(c[3])
        : "r"(a[0]), "r"(a[1]), "r"(a[2]), "r"(a[3]), "r"(b[0]), "r"(b[1]));
}
__device__ __forceinline__ void split2(float v, __nv_bfloat16& h, __nv_bfloat16& l) {
    h = __float2bfloat16(v);
    l = __float2bfloat16(v - __bfloat162float(h));
}
__device__ __forceinline__ void packsplit(float x, float y, uint32_t& hi, uint32_t& lo) {
    __nv_bfloat16 hx, lx, hy, ly;
    split2(x, hx, lx); split2(y, hy, ly);
    __nv_bfloat162 h2 = __halves2bfloat162(hx, hy);
    __nv_bfloat162 l2 = __halves2bfloat162(lx, ly);
    hi = *(uint32_t*)&h2; lo = *(uint32_t*)&l2;
}

// ---------------------------------------------------------------------------
// Pre-split: fp32 -> (hi, lo) bf16, vectorized x4
// ---------------------------------------------------------------------------
__global__ void split_f32(const float* __restrict__ in,
                          __nv_bfloat16* __restrict__ oh,
                          __nv_bfloat16* __restrict__ ol, int n4)
{
    int i = blockIdx.x * blockDim.x + threadIdx.x;
    if (i < n4) {
        float4 f = ((const float4*)in)[i];
        uint32_t h0, l0, h1, l1;
        packsplit(f.x, f.y, h0, l0);
        packsplit(f.z, f.w, h1, l1);
        ((uint2*)oh)[i] = make_uint2(h0, h1);
        ((uint2*)ol)[i] = make_uint2(l0, l1);
    }
}

// ---------------------------------------------------------------------------
// GEMM on pre-split operands: C = A @ W^T + bias (3-pass hi/lo MMA).
// Block 128x128, 256 threads (8 warps: 4m x 2n), K-chunk 32.
// __launch_bounds__(256,2): cap regs at 128 so 2 CTAs/SM stay resident.
// MODE 0: fp32 store. MODE 1: QKV split scatter.
// ---------------------------------------------------------------------------
#define GSTR 40

template<int MODE>
__launch_bounds__(256, 2)
__global__ void gemm_mma(const __nv_bfloat16* __restrict__ Ah, const __nv_bfloat16* __restrict__ Al,
                         const __nv_bfloat16* __restrict__ Wh, const __nv_bfloat16* __restrict__ Wl,
                         const float* __restrict__ bias, float* __restrict__ C,
                         int M, int N, int K)
{
    __shared__ __nv_bfloat16 sAh[128][GSTR], sAl[128][GSTR];
    __shared__ __nv_bfloat16 sBh[128][GSTR], sBl[128][GSTR];

    const int tid = threadIdx.x;
    const int lane = tid & 31, wid = tid >> 5;
    const int gid = lane >> 2, tig = lane & 3;
    const int wm = (wid >> 1) * 32, wn = (wid & 1) * 64;
    const int m0 = blockIdx.y * 128, n0 = blockIdx.x * 128;

    float acc[2][8][4];
    #pragma unroll
    for (int mt = 0; mt < 2; mt++)
        #pragma unroll
        for (int nt = 0; nt < 8; nt++)
            #pragma unroll
            for (int q = 0; q < 4; q++) acc[mt][nt][q] = 0.f;

    for (int k0 = 0; k0 < K; k0 += 32) {
        // stage: pure uint4 copies (8 bf16 each)
        #pragma unroll
        for (int i = 0; i < 2; i++) {
            int idx = tid + i * 256;        // 0..511
            int r = idx >> 2, c = (idx & 3) * 8;
            size_t ga = (size_t)(m0 + r) * K + k0 + c;
            size_t gw = (size_t)(n0 + r) * K + k0 + c;
            *(uint4*)&sAh[r][c] = *(const uint4*)&Ah[ga];
            *(uint4*)&sAl[r][c] = *(const uint4*)&Al[ga];
            *(uint4*)&sBh[r][c] = *(const uint4*)&Wh[gw];
            *(uint4*)&sBl[r][c] = *(const uint4*)&Wl[gw];
        }
        __syncthreads();

        #pragma unroll
        for (int kk = 0; kk < 32; kk += 16) {
            uint32_t ah[2][4], al[2][4];
            #pragma unroll
            for (int mt = 0; mt < 2; mt++) {
                int r = wm + mt * 16 + gid;
                ah[mt][0] = *(uint32_t*)&sAh[r    ][kk + tig*2];
                ah[mt][1] = *(uint32_t*)&sAh[r + 8][kk + tig*2];
                ah[mt][2] = *(uint32_t*)&sAh[r    ][kk + tig*2 + 8];
                ah[mt][3] = *(uint32_t*)&sAh[r + 8][kk + tig*2 + 8];
                al[mt][0] = *(uint32_t*)&sAl[r    ][kk + tig*2];
                al[mt][1] = *(uint32_t*)&sAl[r + 8][kk + tig*2];
                al[mt][2] = *(uint32_t*)&sAl[r    ][kk + tig*2 + 8];
                al[mt][3] = *(uint32_t*)&sAl[r + 8][kk + tig*2 + 8];
            }
            uint32_t bh[8][2], bl[8][2];
            #pragma unroll
            for (int nt = 0; nt < 8; nt++) {
                int rn = wn + nt * 8 + gid;
                bh[nt][0] = *(uint32_t*)&sBh[rn][kk + tig*2];
                bh[nt][1] = *(uint32_t*)&sBh[rn][kk + tig*2 + 8];
                bl[nt][0] = *(uint32_t*)&sBl[rn][kk + tig*2];
                bl[nt][1] = *(uint32_t*)&sBl[rn][kk + tig*2 + 8];
            }
            #pragma unroll
            for (int mt = 0; mt < 2; mt++)
                #pragma unroll
                for (int nt = 0; nt < 8; nt++) {
                    mma16816(acc[mt][nt], ah[mt], bh[nt]);
                    mma16816(acc[mt][nt], ah[mt], bl[nt]);
                    mma16816(acc[mt][nt], al[mt], bh[nt]);
                }
        }
        __syncthreads();
    }

    // Epilogue
    #pragma unroll
    for (int mt = 0; mt < 2; mt++) {
        #pragma unroll
        for (int ih = 0; ih < 2; ih++) {
            int m = m0 + wm + mt * 16 + gid + ih * 8;
            #pragma unroll
            for (int nt = 0; nt < 8; nt++) {
                int n = n0 + wn + nt * 8 + tig * 2;
                float v0 = acc[mt][nt][ih*2 + 0] + __ldg(&bias[n]);
                float v1 = acc[mt][nt][ih*2 + 1] + __ldg(&bias[n + 1]);
                if (MODE == 0) {
                    float2 o2 = { v0, v1 };
                    *(float2*)&C[(size_t)m * N + n] = o2;
                } else {
                    int which = n >> 9, hh = (n >> 6) & 7, dd = n & 63;
                    int bb = m >> 12, s = m & 4095;
                    if (which == 0) {
                        size_t base = (((size_t)(bb * NH + hh) * SEQ) + s) * HDIM + dd;
                        uint32_t hi, lo;
                        packsplit(v0 * 0.125f, v1 * 0.125f, hi, lo);
                        *(uint32_t*)&g_Qh[base] = hi;
                        *(uint32_t*)&g_Ql[base] = lo;
                    } else if (which == 1) {
                        size_t base = (((size_t)(bb * NH + hh) * SEQ) + s) * HDIM + dd;
                        uint32_t hi, lo;
                        packsplit(v0, v1, hi, lo);
                        *(uint32_t*)&g_Kh[base] = hi;
                        *(uint32_t*)&g_Kl[base] = lo;
                    } else {
                        size_t base = ((size_t)(bb * NH + hh) * HDIM + dd) * SEQ + s;
                        __nv_bfloat16 h0, l0, h1, l1;
                        split2(v0, h0, l0); split2(v1, h1, l1);
                        g_Vh[base] = h0;       g_Vl[base] = l0;
                        g_Vh[base + SEQ] = h1; g_Vl[base + SEQ] = l1;
                    }
                }
            }
        }
    }
}

// ---------------------------------------------------------------------------
// Flash attention: Br=128, Bc=64, 8 warps / 256 threads (warp tile 16x64).
// __launch_bounds__(256,2): cap regs at 128 -> 2 CTAs/SM (16 warps resident).
// S 3-pass split; register softmax (4-lane shfl); P from accumulators; P@V 3-pass.
// Epilogue writes split bf16 Y.
// ---------------------------------------------------------------------------
#define FSTR 72
#define QH_OFF 0
#define QL_OFF (128*FSTR*2)
#define KH_OFF (QL_OFF + 128*FSTR*2)
#define KL_OFF (KH_OFF + 64*FSTR*2)
#define VH_OFF (KL_OFF + 64*FSTR*2)
#define VL_OFF (VH_OFF + 64*FSTR*2)
#define FL_SMEM (VL_OFF + 64*FSTR*2)   // 73728 bytes

__launch_bounds__(256, 2)
__global__ void flash_mma()
{
    extern __shared__ char smem[];
    __nv_bfloat16* QH = (__nv_bfloat16*)(smem + QH_OFF);
    __nv_bfloat16* QL = (__nv_bfloat16*)(smem + QL_OFF);
    __nv_bfloat16* KH = (__nv_bfloat16*)(smem + KH_OFF);
    __nv_bfloat16* KL = (__nv_bfloat16*)(smem + KL_OFF);
    __nv_bfloat16* VH = (__nv_bfloat16*)(smem + VH_OFF);
    __nv_bfloat16* VL = (__nv_bfloat16*)(smem + VL_OFF);

    const int tid = threadIdx.x;
    const int lane = tid & 31, wid = tid >> 5;   // wid 0..7
    const int gid = lane >> 2, tig = lane & 3;
    const int qt = (gridDim.x - 1) - blockIdx.x;
    const int head = blockIdx.y;
    const int b = blockIdx.z;

    const size_t bh = (size_t)(b * NH + head);
    const __nv_bfloat16* Qhp = g_Qh + (bh * SEQ + qt * 128) * HDIM;
    const __nv_bfloat16* Qlp = g_Ql + (bh * SEQ + qt * 128) * HDIM;

    // Q tile 128x64 (each buffer)
    #pragma unroll
    for (int i = 0; i < 4; i++) {
        int idx = tid + i * 256;
        int r = idx >> 3, c = (idx & 7) * 8;
        *(uint4*)&QH[r * FSTR + c] = *(const uint4*)&Qhp[r * 64 + c];
        *(uint4*)&QL[r * FSTR + c] = *(const uint4*)&Qlp[r * 64 + c];
    }

    float m_i[2], l_i[2];
    float o[8][4];
    #pragma unroll
    for (int t = 0; t < 2; t++) { m_i[t] = -1e30f; l_i[t] = 0.f; }
    #pragma unroll
    for (int ot = 0; ot < 8; ot++)
        #pragma unroll
        for (int q = 0; q < 4; q++) o[ot][q] = 0.f;

    const int qtr = qt * 128;
    const int nkt = 2 * (qt + 1);

    for (int kt = 0; kt < nkt; kt++) {
        const int kv0 = kt * 64;
        const __nv_bfloat16* Khp = g_Kh + (bh * SEQ + kv0) * HDIM;
        const __nv_bfloat16* Klp = g_Kl + (bh * SEQ + kv0) * HDIM;
        const __nv_bfloat16* Vhp = g_Vh + bh * HDIM * SEQ;
        const __nv_bfloat16* Vlp = g_Vl + bh * HDIM * SEQ;

        __syncthreads();
        #pragma unroll
        for (int i = 0; i < 2; i++) {
            int idx = tid + i * 256;
            int r = idx >> 3, c = (idx & 7) * 8;
            *(uint4*)&KH[r * FSTR + c] = *(const uint4*)&Khp[r * 64 + c];
            *(uint4*)&KL[r * FSTR + c] = *(const uint4*)&Klp[r * 64 + c];
            *(uint4*)&VH[r * FSTR + c] = *(const uint4*)&Vhp[(size_t)r * SEQ + kv0 + c];
            *(uint4*)&VL[r * FSTR + c] = *(const uint4*)&Vlp[(size_t)r * SEQ + kv0 + c];
        }
        __syncthreads();

        // ---- S = Q @ K^T ----
        float s[8][4];
        #pragma unroll
        for (int nt = 0; nt < 8; nt++)
            #pragma unroll
            for (int q = 0; q < 4; q++) s[nt][q] = 0.f;

        #pragma unroll
        for (int ks = 0; ks < 4; ks++) {
            int k0 = ks * 16;
            int r = wid * 16 + gid;
            uint32_t ah[4], al[4];
            ah[0] = *(uint32_t*)&QH[(r    ) * FSTR + k0 + tig*2];
            ah[1] = *(uint32_t*)&QH[(r + 8) * FSTR + k0 + tig*2];
            ah[2] = *(uint32_t*)&QH[(r    ) * FSTR + k0 + tig*2 + 8];
            ah[3] = *(uint32_t*)&QH[(r + 8) * FSTR + k0 + tig*2 + 8];
            al[0] = *(uint32_t*)&QL[(r    ) * FSTR + k0 + tig*2];
            al[1] = *(uint32_t*)&QL[(r + 8) * FSTR + k0 + tig*2];
            al[2] = *(uint32_t*)&QL[(r    ) * FSTR + k0 + tig*2 + 8];
            al[3] = *(uint32_t*)&QL[(r + 8) * FSTR + k0 + tig*2 + 8];
            uint32_t bhf[8][2], blf[8][2];
            #pragma unroll
            for (int nt = 0; nt < 8; nt++) {
                int rn = nt * 8 + gid;
                bhf[nt][0] = *(uint32_t*)&KH[rn * FSTR + k0 + tig*2];
                bhf[nt][1] = *(uint32_t*)&KH[rn * FSTR + k0 + tig*2 + 8];
                blf[nt][0] = *(uint32_t*)&KL[rn * FSTR + k0 + tig*2];
                blf[nt][1] = *(uint32_t*)&KL[rn * FSTR + k0 + tig*2 + 8];
            }
            #pragma unroll
            for (int nt = 0; nt < 8; nt++) {
                mma16816(s[nt], ah, bhf[nt]);
                mma16816(s[nt], ah, blf[nt]);
                mma16816(s[nt], al, bhf[nt]);
            }
        }

        // ---- causal mask ----
        if (kt >= 2 * qt) {
            int row0 = qtr + wid * 16 + gid;
            #pragma unroll
            for (int nt = 0; nt < 8; nt++) {
                int colb = kv0 + nt * 8 + tig * 2;
                if (colb     > row0    ) s[nt][0] = -1e30f;
                if (colb + 1 > row0    ) s[nt][1] = -1e30f;
                if (colb     > row0 + 8) s[nt][2] = -1e30f;
                if (colb + 1 > row0 + 8) s[nt][3] = -1e30f;
            }
        }

        // ---- online softmax ----
        #pragma unroll
        for (int ih = 0; ih < 2; ih++) {
            float mx = m_i[ih];
            #pragma unroll
            for (int nt = 0; nt < 8; nt++)
                mx = fmaxf(mx, fmaxf(s[nt][ih*2], s[nt][ih*2+1]));
            mx = fmaxf(mx, __shfl_xor_sync(0xffffffffu, mx, 1));
            mx = fmaxf(mx, __shfl_xor_sync(0xffffffffu, mx, 2));
            float corr = __expf(m_i[ih] - mx);
            float sum = 0.f;
            #pragma unroll
            for (int nt = 0; nt < 8; nt++) {
                float p0 = __expf(s[nt][ih*2]   - mx);
                float p1 = __expf(s[nt][ih*2+1] - mx);
                s[nt][ih*2]   = p0;
                s[nt][ih*2+1] = p1;
                sum += p0 + p1;
            }
            sum += __shfl_xor_sync(0xffffffffu, sum, 1);
            sum += __shfl_xor_sync(0xffffffffu, sum, 2);
            l_i[ih] = l_i[ih] * corr + sum;
            m_i[ih] = mx;
            #pragma unroll
            for (int ot = 0; ot < 8; ot++) {
                o[ot][ih*2]   *= corr;
                o[ot][ih*2+1] *= corr;
            }
        }

        // ---- O += P @ V ----
        #pragma unroll
        for (int ks = 0; ks < 4; ks++) {
            uint32_t pah[4], pal[4];
            packsplit(s[2*ks  ][0], s[2*ks  ][1], pah[0], pal[0]);
            packsplit(s[2*ks  ][2], s[2*ks  ][3], pah[1], pal[1]);
            packsplit(s[2*ks+1][0], s[2*ks+1][1], pah[2], pal[2]);
            packsplit(s[2*ks+1][2], s[2*ks+1][3], pah[3], pal[3]);
            uint32_t vbh[8][2], vbl[8][2];
            #pragma unroll
            for (int ot = 0; ot < 8; ot++) {
                int rn = ot * 8 + gid;
                vbh[ot][0] = *(uint32_t*)&VH[rn * FSTR + ks*16 + tig*2];
                vbh[ot][1] = *(uint32_t*)&VH[rn * FSTR + ks*16 + tig*2 + 8];
                vbl[ot][0] = *(uint32_t*)&VL[rn * FSTR + ks*16 + tig*2];
                vbl[ot][1] = *(uint32_t*)&VL[rn * FSTR + ks*16 + tig*2 + 8];
            }
            #pragma unroll
            for (int ot = 0; ot < 8; ot++) {
                mma16816(o[ot], pah, vbh[ot]);
                mma16816(o[ot], pal, vbh[ot]);
                mma16816(o[ot], pah, vbl[ot]);
            }
        }
    }

    // ---- epilogue: normalize, write split bf16 Y ----
    size_t Ybase = ((size_t)b * SEQ + qtr) * DIM + head * HDIM;
    #pragma unroll
    for (int ih = 0; ih < 2; ih++) {
        float inv = 1.0f / l_i[ih];
        int rl = wid * 16 + gid + ih * 8;
        #pragma unroll
        for (int ot = 0; ot < 8; ot++) {
            uint32_t hi, lo;
            packsplit(o[ot][ih*2] * inv, o[ot][ih*2+1] * inv, hi, lo);
            size_t off = Ybase + (size_t)rl * DIM + ot * 8 + tig * 2;
            *(uint32_t*)&g_Yh[off] = hi;
            *(uint32_t*)&g_Yl[off] = lo;
        }
    }
}

// ---------------------------------------------------------------------------
extern "C" void kernel_launch(void* const* d_in, const int* in_sizes, int n_in,
                              void* d_out, int out_size)
{
    const float* x    = (const float*)d_in[0];   // [2,4096,512]
    const float* Wqkv = (const float*)d_in[1];   // [1536,512]
    const float* bqkv = (const float*)d_in[2];   // [1536]
    const float* Wo   = (const float*)d_in[3];   // [512,512]
    const float* bo   = (const float*)d_in[4];   // [512]
    float* out = (float*)d_out;                  // [2,4096,512]

    void *xh, *xl, *wqh, *wql, *woh, *wol, *yh, *yl;
    cudaGetSymbolAddress(&xh,  g_Xh);  cudaGetSymbolAddress(&xl,  g_Xl);
    cudaGetSymbolAddress(&wqh, g_Wqh); cudaGetSymbolAddress(&wql, g_Wql);
    cudaGetSymbolAddress(&woh, g_Woh); cudaGetSymbolAddress(&wol, g_Wol);
    cudaGetSymbolAddress(&yh,  g_Yh);  cudaGetSymbolAddress(&yl,  g_Yl);

    cudaFuncSetAttribute(flash_mma, cudaFuncAttributeMaxDynamicSharedMemorySize, FL_SMEM);

    const int M = BSZ * SEQ;   // 8192

    // pre-split inputs
    split_f32<<<(M*DIM/4 + 255)/256, 256>>>(x, (__nv_bfloat16*)xh, (__nv_bfloat16*)xl, M*DIM/4);
    split_f32<<<(3*DIM*DIM/4 + 255)/256, 256>>>(Wqkv, (__nv_bfloat16*)wqh, (__nv_bfloat16*)wql, 3*DIM*DIM/4);
    split_f32<<<(DIM*DIM/4 + 255)/256, 256>>>(Wo, (__nv_bfloat16*)woh, (__nv_bfloat16*)wol, DIM*DIM/4);

    gemm_mma<1><<<dim3(12, 64), 256>>>((const __nv_bfloat16*)xh, (const __nv_bfloat16*)xl,
                                       (const __nv_bfloat16*)wqh, (const __nv_bfloat16*)wql,
                                       bqkv, nullptr, M, 3 * DIM, DIM);
    flash_mma<<<dim3(SEQ / 128, NH, BSZ), 256, FL_SMEM>>>();
    gemm_mma<0><<<dim3(4, 64), 256>>>((const __nv_bfloat16*)yh, (const __nv_bfloat16*)yl,
                                      (const __nv_bfloat16*)woh, (const __nv_bfloat16*)wol,
                                      bo, out, M, DIM, DIM);
}

// round 16
// speedup vs baseline: 1.2025x; 1.1269x over previous
#include <cuda_runtime.h>
#include <cuda_bf16.h>
#include <cstdint>
#include <math.h>

#define BSZ 2
#define SEQ 4096
#define DIM 512
#define NH  8
#define HDIM 64
#define NELEM (BSZ*NH*SEQ*HDIM)
#define MTOT (BSZ*SEQ)

// Scratch (no cudaMalloc). All operands stored as hi/lo split bf16.
__device__ __nv_bfloat16 g_Qh[NELEM], g_Ql[NELEM];
__device__ __nv_bfloat16 g_Kh[NELEM], g_Kl[NELEM];
__device__ __nv_bfloat16 g_Vh[NELEM], g_Vl[NELEM];   // transposed [b,h,hd,s]
__device__ __nv_bfloat16 g_Xh[MTOT*DIM], g_Xl[MTOT*DIM];
__device__ __nv_bfloat16 g_Wqh[3*DIM*DIM], g_Wql[3*DIM*DIM];
__device__ __nv_bfloat16 g_Woh[DIM*DIM], g_Wol[DIM*DIM];
__device__ __nv_bfloat16 g_Yh[MTOT*DIM], g_Yl[MTOT*DIM];

// ---------------------------------------------------------------------------
__device__ __forceinline__ void mma16816(float* c, const uint32_t* a, const uint32_t* b) {
    asm volatile(
        "mma.sync.aligned.m16n8k16.row.col.f32.bf16.bf16.f32 "
        "{%0,%1,%2,%3}, {%4,%5,%6,%7}, {%8,%9}, {%0,%1,%2,%3};"
        : "+f"(c[0]), "+f"(c[1]), "+f"(c[2]), "+f"(c[3])
        : "r"(a[0]), "r"(a[1]), "r"(a[2]), "r"(a[3]), "r"(b[0]), "r"(b[1]));
}
__device__ __forceinline__ void split2(float v, __nv_bfloat16& h, __nv_bfloat16& l) {
    h = __float2bfloat16(v);
    l = __float2bfloat16(v - __bfloat162float(h));
}
__device__ __forceinline__ void packsplit(float x, float y, uint32_t& hi, uint32_t& lo) {
    __nv_bfloat16 hx, lx, hy, ly;
    split2(x, hx, lx); split2(y, hy, ly);
    __nv_bfloat162 h2 = __halves2bfloat162(hx, hy);
    __nv_bfloat162 l2 = __halves2bfloat162(lx, ly);
    hi = *(uint32_t*)&h2; lo = *(uint32_t*)&l2;
}
__device__ __forceinline__ uint32_t smem_u32(const void* p) {
    uint32_t a;
    asm("{ .reg .u64 t; cvta.to.shared.u64 t, %1; cvt.u32.u64 %0, t; }" : "=r"(a) : "l"(p));
    return a;
}
__device__ __forceinline__ void cp16(uint32_t dst, const void* src) {
    asm volatile("cp.async.cg.shared.global [%0], [%1], 16;" :: "r"(dst), "l"(src));
}
#define CP_COMMIT() asm volatile("cp.async.commit_group;" ::: "memory")
#define CP_WAIT1()  asm volatile("cp.async.wait_group 1;" ::: "memory")

// ---------------------------------------------------------------------------
// Pre-split: fp32 -> (hi, lo) bf16, vectorized x4
// ---------------------------------------------------------------------------
__global__ void split_f32(const float* __restrict__ in,
                          __nv_bfloat16* __restrict__ oh,
                          __nv_bfloat16* __restrict__ ol, int n4)
{
    int i = blockIdx.x * blockDim.x + threadIdx.x;
    if (i < n4) {
        float4 f = ((const float4*)in)[i];
        uint32_t h0, l0, h1, l1;
        packsplit(f.x, f.y, h0, l0);
        packsplit(f.z, f.w, h1, l1);
        ((uint2*)oh)[i] = make_uint2(h0, h1);
        ((uint2*)ol)[i] = make_uint2(l0, l1);
    }
}

// ---------------------------------------------------------------------------
// GEMM, cp.async double-buffered: C = A @ W^T + bias (3-pass hi/lo MMA).
// Block 128x128, 256 threads (8 warps: 4m x 2n), K-chunk 32, 2 stages.
// ---------------------------------------------------------------------------
#define GSTR 40
#define G_ARR  10240                 // bytes per array: 128*40*2
#define G_STAGE (4*G_ARR)            // 40960
#define G_SMEM  (2*G_STAGE)          // 81920

template<int MODE>
__launch_bounds__(256, 2)
__global__ void gemm_mma(const __nv_bfloat16* __restrict__ Ah, const __nv_bfloat16* __restrict__ Al,
                         const __nv_bfloat16* __restrict__ Wh, const __nv_bfloat16* __restrict__ Wl,
                         const float* __restrict__ bias, float* __restrict__ C,
                         int M, int N, int K)
{
    extern __shared__ char smem[];
    const uint32_t sbase = smem_u32(smem);

    const int tid = threadIdx.x;
    const int lane = tid & 31, wid = tid >> 5;
    const int gid = lane >> 2, tig = lane & 3;
    const int wm = (wid >> 1) * 32, wn = (wid & 1) * 64;
    const int m0 = blockIdx.y * 128, n0 = blockIdx.x * 128;

    float acc[2][8][4];
    #pragma unroll
    for (int mt = 0; mt < 2; mt++)
        #pragma unroll
        for (int nt = 0; nt < 8; nt++)
            #pragma unroll
            for (int q = 0; q < 4; q++) acc[mt][nt][q] = 0.f;

    const int niter = K / 32;

    // issue stage fill via cp.async (2048 x 16B per stage)
    auto issue = [&](int it, int stg) {
        const int k0 = it * 32;
        const uint32_t so = sbase + stg * G_STAGE;
        #pragma unroll
        for (int i = 0; i < 2; i++) {
            int idx = tid + i * 256;
            int r = idx >> 2, c = (idx & 3) * 8;
            uint32_t doff = r * (GSTR * 2) + c * 2;
            size_t ga = (size_t)(m0 + r) * K + k0 + c;
            size_t gw = (size_t)(n0 + r) * K + k0 + c;
            cp16(so + 0*G_ARR + doff, Ah + ga);
            cp16(so + 1*G_ARR + doff, Al + ga);
            cp16(so + 2*G_ARR + doff, Wh + gw);
            cp16(so + 3*G_ARR + doff, Wl + gw);
        }
    };

    issue(0, 0);
    CP_COMMIT();

    for (int it = 0; it < niter; it++) {
        if (it + 1 < niter) issue(it + 1, (it + 1) & 1);
        CP_COMMIT();
        CP_WAIT1();
        __syncthreads();

        char* st = smem + (it & 1) * G_STAGE;
        __nv_bfloat16 (*sAh)[GSTR] = (__nv_bfloat16(*)[GSTR])(st);
        __nv_bfloat16 (*sAl)[GSTR] = (__nv_bfloat16(*)[GSTR])(st + G_ARR);
        __nv_bfloat16 (*sBh)[GSTR] = (__nv_bfloat16(*)[GSTR])(st + 2*G_ARR);
        __nv_bfloat16 (*sBl)[GSTR] = (__nv_bfloat16(*)[GSTR])(st + 3*G_ARR);

        #pragma unroll
        for (int kk = 0; kk < 32; kk += 16) {
            uint32_t ah[2][4], al[2][4];
            #pragma unroll
            for (int mt = 0; mt < 2; mt++) {
                int r = wm + mt * 16 + gid;
                ah[mt][0] = *(uint32_t*)&sAh[r    ][kk + tig*2];
                ah[mt][1] = *(uint32_t*)&sAh[r + 8][kk + tig*2];
                ah[mt][2] = *(uint32_t*)&sAh[r    ][kk + tig*2 + 8];
                ah[mt][3] = *(uint32_t*)&sAh[r + 8][kk + tig*2 + 8];
                al[mt][0] = *(uint32_t*)&sAl[r    ][kk + tig*2];
                al[mt][1] = *(uint32_t*)&sAl[r + 8][kk + tig*2];
                al[mt][2] = *(uint32_t*)&sAl[r    ][kk + tig*2 + 8];
                al[mt][3] = *(uint32_t*)&sAl[r + 8][kk + tig*2 + 8];
            }
            uint32_t bh[8][2], bl[8][2];
            #pragma unroll
            for (int nt = 0; nt < 8; nt++) {
                int rn = wn + nt * 8 + gid;
                bh[nt][0] = *(uint32_t*)&sBh[rn][kk + tig*2];
                bh[nt][1] = *(uint32_t*)&sBh[rn][kk + tig*2 + 8];
                bl[nt][0] = *(uint32_t*)&sBl[rn][kk + tig*2];
                bl[nt][1] = *(uint32_t*)&sBl[rn][kk + tig*2 + 8];
            }
            #pragma unroll
            for (int mt = 0; mt < 2; mt++)
                #pragma unroll
                for (int nt = 0; nt < 8; nt++) {
                    mma16816(acc[mt][nt], ah[mt], bh[nt]);
                    mma16816(acc[mt][nt], ah[mt], bl[nt]);
                    mma16816(acc[mt][nt], al[mt], bh[nt]);
                }
        }
        __syncthreads();
    }

    // Epilogue
    #pragma unroll
    for (int mt = 0; mt < 2; mt++) {
        #pragma unroll
        for (int ih = 0; ih < 2; ih++) {
            int m = m0 + wm + mt * 16 + gid + ih * 8;
            #pragma unroll
            for (int nt = 0; nt < 8; nt++) {
                int n = n0 + wn + nt * 8 + tig * 2;
                float v0 = acc[mt][nt][ih*2 + 0] + __ldg(&bias[n]);
                float v1 = acc[mt][nt][ih*2 + 1] + __ldg(&bias[n + 1]);
                if (MODE == 0) {
                    float2 o2 = { v0, v1 };
                    *(float2*)&C[(size_t)m * N + n] = o2;
                } else {
                    int which = n >> 9, hh = (n >> 6) & 7, dd = n & 63;
                    int bb = m >> 12, s = m & 4095;
                    if (which == 0) {
                        size_t base = (((size_t)(bb * NH + hh) * SEQ) + s) * HDIM + dd;
                        uint32_t hi, lo;
                        packsplit(v0 * 0.125f, v1 * 0.125f, hi, lo);
                        *(uint32_t*)&g_Qh[base] = hi;
                        *(uint32_t*)&g_Ql[base] = lo;
                    } else if (which == 1) {
                        size_t base = (((size_t)(bb * NH + hh) * SEQ) + s) * HDIM + dd;
                        uint32_t hi, lo;
                        packsplit(v0, v1, hi, lo);
                        *(uint32_t*)&g_Kh[base] = hi;
                        *(uint32_t*)&g_Kl[base] = lo;
                    } else {
                        size_t base = ((size_t)(bb * NH + hh) * HDIM + dd) * SEQ + s;
                        __nv_bfloat16 h0, l0, h1, l1;
                        split2(v0, h0, l0); split2(v1, h1, l1);
                        g_Vh[base] = h0;       g_Vl[base] = l0;
                        g_Vh[base + SEQ] = h1; g_Vl[base + SEQ] = l1;
                    }
                }
            }
        }
    }
}

// ---------------------------------------------------------------------------
// Flash attention: Br=128, Bc=64, 4 warps / 128 threads (warp tile 32x64),
// cp.async double-buffered K/V (2 stages). Split bf16 Y epilogue.
// ---------------------------------------------------------------------------
#define FSTR 72
#define F_ARR   9216                 // 64*72*2
#define F_STAGE (4*F_ARR)            // 36864: KH, KL, VH, VL
#define FQ_BYTES (2*128*FSTR*2)      // 36864: QH + QL
#define FL_SMEM (FQ_BYTES + 2*F_STAGE)   // 110592

__global__ void flash_mma()
{
    extern __shared__ char smem[];
    const uint32_t sbase = smem_u32(smem);
    __nv_bfloat16* QH = (__nv_bfloat16*)(smem);
    __nv_bfloat16* QL = (__nv_bfloat16*)(smem + 128*FSTR*2);

    const int tid = threadIdx.x;
    const int lane = tid & 31, wid = tid >> 5;   // 4 warps
    const int gid = lane >> 2, tig = lane & 3;
    const int qt = (gridDim.x - 1) - blockIdx.x;
    const int head = blockIdx.y;
    const int b = blockIdx.z;

    const size_t bh = (size_t)(b * NH + head);
    const __nv_bfloat16* Qhp = g_Qh + (bh * SEQ + qt * 128) * HDIM;
    const __nv_bfloat16* Qlp = g_Ql + (bh * SEQ + qt * 128) * HDIM;
    const __nv_bfloat16* Khp = g_Kh + bh * SEQ * HDIM;
    const __nv_bfloat16* Klp = g_Kl + bh * SEQ * HDIM;
    const __nv_bfloat16* Vhp = g_Vh + bh * HDIM * SEQ;   // [hd][s]
    const __nv_bfloat16* Vlp = g_Vl + bh * HDIM * SEQ;

    // Q tile (plain loads, once)
    #pragma unroll
    for (int i = 0; i < 8; i++) {
        int idx = tid + i * 128;
        int r = idx >> 3, c = (idx & 7) * 8;
        *(uint4*)&QH[r * FSTR + c] = *(const uint4*)&Qhp[r * 64 + c];
        *(uint4*)&QL[r * FSTR + c] = *(const uint4*)&Qlp[r * 64 + c];
    }

    float m_i[4], l_i[4];
    float o[2][8][4];
    #pragma unroll
    for (int t = 0; t < 4; t++) { m_i[t] = -1e30f; l_i[t] = 0.f; }
    #pragma unroll
    for (int mt = 0; mt < 2; mt++)
        #pragma unroll
        for (int ot = 0; ot < 8; ot++)
            #pragma unroll
            for (int q = 0; q < 4; q++) o[mt][ot][q] = 0.f;

    const int qtr = qt * 128;
    const int nkt = 2 * (qt + 1);

    // issue K/V stage fill via cp.async
    auto issue = [&](int kt, int stg) {
        const int kv0 = kt * 64;
        const uint32_t so = sbase + FQ_BYTES + stg * F_STAGE;
        #pragma unroll
        for (int i = 0; i < 4; i++) {
            int idx = tid + i * 128;
            int r = idx >> 3, c = (idx & 7) * 8;
            uint32_t doff = r * (FSTR * 2) + c * 2;
            cp16(so + 0*F_ARR + doff, Khp + (size_t)(kv0 + r) * 64 + c);
            cp16(so + 1*F_ARR + doff, Klp + (size_t)(kv0 + r) * 64 + c);
            cp16(so + 2*F_ARR + doff, Vhp + (size_t)r * SEQ + kv0 + c);
            cp16(so + 3*F_ARR + doff, Vlp + (size_t)r * SEQ + kv0 + c);
        }
    };

    issue(0, 0);
    CP_COMMIT();

    for (int kt = 0; kt < nkt; kt++) {
        if (kt + 1 < nkt) issue(kt + 1, (kt + 1) & 1);
        CP_COMMIT();
        CP_WAIT1();
        __syncthreads();

        char* st = smem + FQ_BYTES + (kt & 1) * F_STAGE;
        __nv_bfloat16* KH = (__nv_bfloat16*)(st);
        __nv_bfloat16* KL = (__nv_bfloat16*)(st + F_ARR);
        __nv_bfloat16* VH = (__nv_bfloat16*)(st + 2*F_ARR);
        __nv_bfloat16* VL = (__nv_bfloat16*)(st + 3*F_ARR);
        const int kv0 = kt * 64;

        // ---- S = Q @ K^T ----
        float s[2][8][4];
        #pragma unroll
        for (int mt = 0; mt < 2; mt++)
            #pragma unroll
            for (int nt = 0; nt < 8; nt++)
                #pragma unroll
                for (int q = 0; q < 4; q++) s[mt][nt][q] = 0.f;

        #pragma unroll
        for (int ks = 0; ks < 4; ks++) {
            int k0 = ks * 16;
            uint32_t ah[2][4], al[2][4];
            #pragma unroll
            for (int mt = 0; mt < 2; mt++) {
                int r = wid * 32 + mt * 16 + gid;
                ah[mt][0] = *(uint32_t*)&QH[(r    ) * FSTR + k0 + tig*2];
                ah[mt][1] = *(uint32_t*)&QH[(r + 8) * FSTR + k0 + tig*2];
                ah[mt][2] = *(uint32_t*)&QH[(r    ) * FSTR + k0 + tig*2 + 8];
                ah[mt][3] = *(uint32_t*)&QH[(r + 8) * FSTR + k0 + tig*2 + 8];
                al[mt][0] = *(uint32_t*)&QL[(r    ) * FSTR + k0 + tig*2];
                al[mt][1] = *(uint32_t*)&QL[(r + 8) * FSTR + k0 + tig*2];
                al[mt][2] = *(uint32_t*)&QL[(r    ) * FSTR + k0 + tig*2 + 8];
                al[mt][3] = *(uint32_t*)&QL[(r + 8) * FSTR + k0 + tig*2 + 8];
            }
            uint32_t bhf[8][2], blf[8][2];
            #pragma unroll
            for (int nt = 0; nt < 8; nt++) {
                int rn = nt * 8 + gid;
                bhf[nt][0] = *(uint32_t*)&KH[rn * FSTR + k0 + tig*2];
                bhf[nt][1] = *(uint32_t*)&KH[rn * FSTR + k0 + tig*2 + 8];
                blf[nt][0] = *(uint32_t*)&KL[rn * FSTR + k0 + tig*2];
                blf[nt][1] = *(uint32_t*)&KL[rn * FSTR + k0 + tig*2 + 8];
            }
            #pragma unroll
            for (int mt = 0; mt < 2; mt++)
                #pragma unroll
                for (int nt = 0; nt < 8; nt++) {
                    mma16816(s[mt][nt], ah[mt], bhf[nt]);
                    mma16816(s[mt][nt], ah[mt], blf[nt]);
                    mma16816(s[mt][nt], al[mt], bhf[nt]);
                }
        }

        // ---- causal mask ----
        if (kt >= 2 * qt) {
            #pragma unroll
            for (int mt = 0; mt < 2; mt++) {
                int row0 = qtr + wid * 32 + mt * 16 + gid;
                #pragma unroll
                for (int nt = 0; nt < 8; nt++) {
                    int colb = kv0 + nt * 8 + tig * 2;
                    if (colb     > row0    ) s[mt][nt][0] = -1e30f;
                    if (colb + 1 > row0    ) s[mt][nt][1] = -1e30f;
                    if (colb     > row0 + 8) s[mt][nt][2] = -1e30f;
                    if (colb + 1 > row0 + 8) s[mt][nt][3] = -1e30f;
                }
            }
        }

        // ---- online softmax ----
        #pragma unroll
        for (int mt = 0; mt < 2; mt++) {
            #pragma unroll
            for (int ih = 0; ih < 2; ih++) {
                int si = mt * 2 + ih;
                float mx = m_i[si];
                #pragma unroll
                for (int nt = 0; nt < 8; nt++)
                    mx = fmaxf(mx, fmaxf(s[mt][nt][ih*2], s[mt][nt][ih*2+1]));
                mx = fmaxf(mx, __shfl_xor_sync(0xffffffffu, mx, 1));
                mx = fmaxf(mx, __shfl_xor_sync(0xffffffffu, mx, 2));
                float corr = __expf(m_i[si] - mx);
                float sum = 0.f;
                #pragma unroll
                for (int nt = 0; nt < 8; nt++) {
                    float p0 = __expf(s[mt][nt][ih*2]   - mx);
                    float p1 = __expf(s[mt][nt][ih*2+1] - mx);
                    s[mt][nt][ih*2]   = p0;
                    s[mt][nt][ih*2+1] = p1;
                    sum += p0 + p1;
                }
                sum += __shfl_xor_sync(0xffffffffu, sum, 1);
                sum += __shfl_xor_sync(0xffffffffu, sum, 2);
                l_i[si] = l_i[si] * corr + sum;
                m_i[si] = mx;
                #pragma unroll
                for (int ot = 0; ot < 8; ot++) {
                    o[mt][ot][ih*2]   *= corr;
                    o[mt][ot][ih*2+1] *= corr;
                }
            }
        }

        // ---- O += P @ V ----
        #pragma unroll
        for (int ks = 0; ks < 4; ks++) {
            uint32_t pah[2][4], pal[2][4];
            #pragma unroll
            for (int mt = 0; mt < 2; mt++) {
                packsplit(s[mt][2*ks  ][0], s[mt][2*ks  ][1], pah[mt][0], pal[mt][0]);
                packsplit(s[mt][2*ks  ][2], s[mt][2*ks  ][3], pah[mt][1], pal[mt][1]);
                packsplit(s[mt][2*ks+1][0], s[mt][2*ks+1][1], pah[mt][2], pal[mt][2]);
                packsplit(s[mt][2*ks+1][2], s[mt][2*ks+1][3], pah[mt][3], pal[mt][3]);
            }
            uint32_t vbh[8][2], vbl[8][2];
            #pragma unroll
            for (int ot = 0; ot < 8; ot++) {
                int rn = ot * 8 + gid;
                vbh[ot][0] = *(uint32_t*)&VH[rn * FSTR + ks*16 + tig*2];
                vbh[ot][1] = *(uint32_t*)&VH[rn * FSTR + ks*16 + tig*2 + 8];
                vbl[ot][0] = *(uint32_t*)&VL[rn * FSTR + ks*16 + tig*2];
                vbl[ot][1] = *(uint32_t*)&VL[rn * FSTR + ks*16 + tig*2 + 8];
            }
            #pragma unroll
            for (int mt = 0; mt < 2; mt++)
                #pragma unroll
                for (int ot = 0; ot < 8; ot++) {
                    mma16816(o[mt][ot], pah[mt], vbh[ot]);
                    mma16816(o[mt][ot], pal[mt], vbh[ot]);
                    mma16816(o[mt][ot], pah[mt], vbl[ot]);
                }
        }
        __syncthreads();
    }

    // ---- epilogue: normalize, write split bf16 Y ----
    size_t Ybase = ((size_t)b * SEQ + qtr) * DIM + head * HDIM;
    #pragma unroll
    for (int mt = 0; mt < 2; mt++) {
        #pragma unroll
        for (int ih = 0; ih < 2; ih++) {
            float inv = 1.0f / l_i[mt * 2 + ih];
            int rl = wid * 32 + mt * 16 + gid + ih * 8;
            #pragma unroll
            for (int ot = 0; ot < 8; ot++) {
                uint32_t hi, lo;
                packsplit(o[mt][ot][ih*2] * inv, o[mt][ot][ih*2+1] * inv, hi, lo);
                size_t off = Ybase + (size_t)rl * DIM + ot * 8 + tig * 2;
                *(uint32_t*)&g_Yh[off] = hi;
                *(uint32_t*)&g_Yl[off] = lo;
            }
        }
    }
}

// ---------------------------------------------------------------------------
extern "C" void kernel_launch(void* const* d_in, const int* in_sizes, int n_in,
                              void* d_out, int out_size)
{
    const float* x    = (const float*)d_in[0];   // [2,4096,512]
    const float* Wqkv = (const float*)d_in[1];   // [1536,512]
    const float* bqkv = (const float*)d_in[2];   // [1536]
    const float* Wo   = (const float*)d_in[3];   // [512,512]
    const float* bo   = (const float*)d_in[4];   // [512]
    float* out = (float*)d_out;                  // [2,4096,512]

    void *xh, *xl, *wqh, *wql, *woh, *wol, *yh, *yl;
    cudaGetSymbolAddress(&xh,  g_Xh);  cudaGetSymbolAddress(&xl,  g_Xl);
    cudaGetSymbolAddress(&wqh, g_Wqh); cudaGetSymbolAddress(&wql, g_Wql);
    cudaGetSymbolAddress(&woh, g_Woh); cudaGetSymbolAddress(&wol, g_Wol);
    cudaGetSymbolAddress(&yh,  g_Yh);  cudaGetSymbolAddress(&yl,  g_Yl);

    cudaFuncSetAttribute(gemm_mma<1>, cudaFuncAttributeMaxDynamicSharedMemorySize, G_SMEM);
    cudaFuncSetAttribute(gemm_mma<0>, cudaFuncAttributeMaxDynamicSharedMemorySize, G_SMEM);
    cudaFuncSetAttribute(flash_mma, cudaFuncAttributeMaxDynamicSharedMemorySize, FL_SMEM);

    const int M = BSZ * SEQ;   // 8192

    split_f32<<<(M*DIM/4 + 255)/256, 256>>>(x, (__nv_bfloat16*)xh, (__nv_bfloat16*)xl, M*DIM/4);
    split_f32<<<(3*DIM*DIM/4 + 255)/256, 256>>>(Wqkv, (__nv_bfloat16*)wqh, (__nv_bfloat16*)wql, 3*DIM*DIM/4);
    split_f32<<<(DIM*DIM/4 + 255)/256, 256>>>(Wo, (__nv_bfloat16*)woh, (__nv_bfloat16*)wol, DIM*DIM/4);

    gemm_mma<1><<<dim3(12, 64), 256, G_SMEM>>>((const __nv_bfloat16*)xh, (const __nv_bfloat16*)xl,
                                               (const __nv_bfloat16*)wqh, (const __nv_bfloat16*)wql,
                                               bqkv, nullptr, M, 3 * DIM, DIM);
    flash_mma<<<dim3(SEQ / 128, NH, BSZ), 128, FL_SMEM>>>();
    gemm_mma<0><<<dim3(4, 64), 256, G_SMEM>>>((const __nv_bfloat16*)yh, (const __nv_bfloat16*)yl,
                                              (const __nv_bfloat16*)woh, (const __nv_bfloat16*)wol,
                                              bo, out, M, DIM, DIM);
}